// round 13
// baseline (speedup 1.0000x reference)
#include <cuda_runtime.h>
#include <cstdint>
#include <cstddef>

#define BB 1024
#define FF 4096
#define DD 32
#define NT 4             // n-tiles of 8: n 0-31 embed (bias via FFMA)
#define MTILES 4         // 256 rows per mtile
#define KSPLITS 64
#define K_PER_CTA 64
#define KC 32
#define A_STRIDE 68      // 64 k + 4 pad: conflict-free, 16B aligned
#define B_STRIDE 40      // cols 0-31 embed, col 32 bias
#define NBP 36           // partials row stride (0-31 s, 32 bias)
#define NCTAS (MTILES * KSPLITS)     // 256
#define SMEM_FLOATS (256 * A_STRIDE + K_PER_CTA * B_STRIDE)   // 19968 -> 78 KB

__device__ float g_part[(size_t)KSPLITS * BB * NBP];
__device__ volatile unsigned g_phase[MTILES];      // monotonic epochs (static-zero)
__device__ unsigned g_c1[MTILES * 8];              // level-1 counters (8 arrivals each)
__device__ unsigned g_c2[MTILES];                  // level-2 counters (8 arrivals)

__device__ __forceinline__ uint32_t smem_u32(const void* p) {
    uint32_t a;
    asm("{ .reg .u64 t; cvta.to.shared.u64 t, %1; cvt.u32.u64 %0, t; }" : "=r"(a) : "l"(p));
    return a;
}
__device__ __forceinline__ void cp16(uint32_t dst, const void* src) {
    asm volatile("cp.async.cg.shared.global [%0], [%1], 16;" :: "r"(dst), "l"(src));
}
__device__ __forceinline__ void cp4(uint32_t dst, const void* src) {
    asm volatile("cp.async.ca.shared.global [%0], [%1], 4;" :: "r"(dst), "l"(src));
}
__device__ __forceinline__ void cp_commit() { asm volatile("cp.async.commit_group;"); }
template <int N>
__device__ __forceinline__ void cp_wait() { asm volatile("cp.async.wait_group %0;" :: "n"(N)); }

// ---------------- single fused kernel ----------------
__global__ void __launch_bounds__(256, 2)
fm_fused(const float* __restrict__ data,
         const float* __restrict__ embed,
         const float* __restrict__ bias,
         const float* __restrict__ gbias,
         float* __restrict__ out)
{
    extern __shared__ float sm[];
    float* As = sm;                       // [row][k] stride 68, 256 rows
    float* Bs = sm + 256 * A_STRIDE;      // [k][n]  stride 40, 64 k-rows

    const int t = threadIdx.x;
    const int w = t >> 5, lane = t & 31;
    const int g = lane >> 2, ctg = lane & 3;
    const int mtile = blockIdx.x & (MTILES - 1);
    const int ksplit = blockIdx.x >> 2;
    const int kbase = ksplit * K_PER_CTA;
    const float* arow0 = data + (size_t)(mtile * 256) * FF + kbase;

    const unsigned my_epoch = g_phase[mtile];   // snapshot BEFORE arriving

    // ---- issue all loads: 2 commit groups of 32 k each ----
    #pragma unroll
    for (int c = 0; c < 2; c++) {
        #pragma unroll
        for (int i = 0; i < 8; i++) {                 // A: 256 rows x 8 float4 per chunk
            const int idx = t + i * 256;
            const int row = idx >> 3, kq = (idx & 7) << 2;
            cp16(smem_u32(&As[row * A_STRIDE + c * KC + kq]),
                 arow0 + (size_t)row * FF + c * KC + kq);
        }
        {                                             // B: 32 k-rows x 8 float4
            const int k = t >> 3, q4 = (t & 7) << 2;
            cp16(smem_u32(&Bs[(c * KC + k) * B_STRIDE + q4]),
                 embed + (size_t)(kbase + c * KC + k) * DD + q4);
        }
        if (t < KC)
            cp4(smem_u32(&Bs[(c * KC + t) * B_STRIDE + 32]), bias + kbase + c * KC + t);
        cp_commit();
    }

    float acc[2][NT][4];
    #pragma unroll
    for (int f = 0; f < 2; f++)
        #pragma unroll
        for (int nt = 0; nt < NT; nt++)
            #pragma unroll
            for (int j = 0; j < 4; j++) acc[f][nt][j] = 0.f;
    float bacc[4] = {0.f, 0.f, 0.f, 0.f};

    const float* Aw = &As[(w * 32) * A_STRIDE];       // warp owns 32 rows

    #pragma unroll
    for (int ch = 0; ch < 2; ch++) {
        if (ch == 0) cp_wait<1>();
        else         cp_wait<0>();
        __syncthreads();

        #pragma unroll
        for (int ks = 0; ks < 4; ks++) {
            const int k0 = ch * KC + ks * 8;
            uint32_t a[2][4];
            #pragma unroll
            for (int f = 0; f < 2; f++) {
                const float* Af = Aw + f * 16 * A_STRIDE;
                a[f][0] = __float_as_uint(Af[g * A_STRIDE + k0 + ctg]);
                a[f][1] = __float_as_uint(Af[(g + 8) * A_STRIDE + k0 + ctg]);
                a[f][2] = __float_as_uint(Af[g * A_STRIDE + k0 + ctg + 4]);
                a[f][3] = __float_as_uint(Af[(g + 8) * A_STRIDE + k0 + ctg + 4]);
            }
            // bias column via scalar FFMA (fma pipe is idle)
            const float bk  = Bs[(k0 + ctg) * B_STRIDE + 32];
            const float bk4 = Bs[(k0 + ctg + 4) * B_STRIDE + 32];
            bacc[0] = fmaf(__uint_as_float(a[0][0]), bk,  bacc[0]);
            bacc[0] = fmaf(__uint_as_float(a[0][2]), bk4, bacc[0]);
            bacc[1] = fmaf(__uint_as_float(a[0][1]), bk,  bacc[1]);
            bacc[1] = fmaf(__uint_as_float(a[0][3]), bk4, bacc[1]);
            bacc[2] = fmaf(__uint_as_float(a[1][0]), bk,  bacc[2]);
            bacc[2] = fmaf(__uint_as_float(a[1][2]), bk4, bacc[2]);
            bacc[3] = fmaf(__uint_as_float(a[1][1]), bk,  bacc[3]);
            bacc[3] = fmaf(__uint_as_float(a[1][3]), bk4, bacc[3]);

            #pragma unroll
            for (int nt = 0; nt < NT; nt++) {
                const uint32_t b0 = __float_as_uint(Bs[(k0 + ctg) * B_STRIDE + nt * 8 + g]);
                const uint32_t b1 = __float_as_uint(Bs[(k0 + ctg + 4) * B_STRIDE + nt * 8 + g]);
                #pragma unroll
                for (int f = 0; f < 2; f++) {
                    asm volatile(
                        "mma.sync.aligned.m16n8k8.row.col.f32.tf32.tf32.f32 "
                        "{%0,%1,%2,%3}, {%4,%5,%6,%7}, {%8,%9}, {%0,%1,%2,%3};"
                        : "+f"(acc[f][nt][0]), "+f"(acc[f][nt][1]),
                          "+f"(acc[f][nt][2]), "+f"(acc[f][nt][3])
                        : "r"(a[f][0]), "r"(a[f][1]), "r"(a[f][2]), "r"(a[f][3]),
                          "r"(b0), "r"(b1));
                }
            }
        }
    }

    // ---- epilogue: plain stores into this ksplit's private slab ----
    float* pbase = g_part + (size_t)ksplit * BB * NBP;
    const int mbase = mtile * 256 + w * 32;
    #pragma unroll
    for (int f = 0; f < 2; f++) {
        #pragma unroll
        for (int nt = 0; nt < NT; nt++) {
            #pragma unroll
            for (int j = 0; j < 4; j++) {
                const int n = nt * 8 + 2 * ctg + (j & 1);
                const int m = mbase + f * 16 + g + ((j >> 1) << 3);
                pbase[(size_t)m * NBP + n] = acc[f][nt][j];
            }
        }
    }
    // bias partials: quad-reduce, ctg==0 stores 4 rows
    #pragma unroll
    for (int q = 0; q < 4; q++) {
        bacc[q] += __shfl_xor_sync(0xffffffffu, bacc[q], 1);
        bacc[q] += __shfl_xor_sync(0xffffffffu, bacc[q], 2);
    }
    if (ctg == 0) {
        pbase[(size_t)(mbase + g) * NBP + 32]      = bacc[0];
        pbase[(size_t)(mbase + g + 8) * NBP + 32]  = bacc[1];
        pbase[(size_t)(mbase + 16 + g) * NBP + 32] = bacc[2];
        pbase[(size_t)(mbase + 24 + g) * NBP + 32] = bacc[3];
    }

    // ---- per-mtile two-level tree barrier (64 arrivals: 8 groups x 8) ----
    __threadfence();
    __syncthreads();
    if (t == 0) {
        const int grp = mtile * 8 + (ksplit >> 3);
        if (atomicAdd(&g_c1[grp], 1u) == 7u) {
            if (atomicAdd(&g_c2[mtile], 1u) == 7u) {
                // last group leader: reset counters, release this mtile
                g_c2[mtile] = 0u;
                #pragma unroll
                for (int i = 0; i < 8; i++) g_c1[mtile * 8 + i] = 0u;
                __threadfence();
                atomicAdd((unsigned*)&g_phase[mtile], 1u);
            }
        }
        while (g_phase[mtile] == my_epoch) {}
    }
    __syncthreads();
    __threadfence();

    // ---- finish: warps 0-3 each own one row inside this mtile ----
    if (w < 4) {
        const int row = mtile * 256 + ksplit * 4 + w;
        float s = 0.f;
        #pragma unroll
        for (int k = 0; k < KSPLITS; k++)
            s += g_part[((size_t)k * BB + row) * NBP + lane];

        const float b = g_part[((size_t)lane * BB + row) * NBP + 32]
                      + g_part[((size_t)(lane + 32) * BB + row) * NBP + 32];

        float v = s * s + b;
        #pragma unroll
        for (int o = 16; o; o >>= 1)
            v += __shfl_xor_sync(0xffffffffu, v, o);

        if (lane == 0)
            out[row] = 1.0f / (1.0f + __expf(-(gbias[0] + v)));
    }
}

extern "C" void kernel_launch(void* const* d_in, const int* in_sizes, int n_in,
                              void* d_out, int out_size)
{
    const float* data  = (const float*)d_in[0];
    const float* embed = (const float*)d_in[1];
    const float* bias  = (const float*)d_in[2];
    const float* gb    = (const float*)d_in[3];
    float* out = (float*)d_out;

    const int smem_bytes = SMEM_FLOATS * (int)sizeof(float);
    cudaFuncSetAttribute(fm_fused, cudaFuncAttributeMaxDynamicSharedMemorySize, smem_bytes);

    fm_fused<<<NCTAS, 256, smem_bytes>>>(data, embed, bias, gb, out);
}

// round 14
// speedup vs baseline: 1.1356x; 1.1356x over previous
#include <cuda_runtime.h>
#include <cstdint>
#include <cstddef>

#define BB 1024
#define FF 4096
#define DD 32
#define NT 5             // n-tiles of 8: n 0-31 embed, 32 bias, 33-39 zero pad
#define MTILES 8
#define KSPLITS 32
#define K_PER_CTA 128
#define KC 32
#define NCHUNK 4
#define A_STRIDE 132     // conflict-free, 16B aligned
#define B_STRIDE 40
#define NBP 36
#define NCTAS (MTILES * KSPLITS)     // 256
#define SMEM_FLOATS (128 * A_STRIDE + K_PER_CTA * B_STRIDE)   // 86 KB

__device__ float g_part[(size_t)KSPLITS * BB * NBP];
__device__ volatile unsigned g_phase[MTILES];   // monotonic epochs (static-zero)
__device__ unsigned g_c1[MTILES * 4];           // level-1: 8 arrivals each
__device__ unsigned g_c2[MTILES];               // level-2: 4 arrivals

__device__ __forceinline__ uint32_t smem_u32(const void* p) {
    uint32_t a;
    asm("{ .reg .u64 t; cvta.to.shared.u64 t, %1; cvt.u32.u64 %0, t; }" : "=r"(a) : "l"(p));
    return a;
}
__device__ __forceinline__ void cp16(uint32_t dst, const void* src) {
    asm volatile("cp.async.cg.shared.global [%0], [%1], 16;" :: "r"(dst), "l"(src));
}
__device__ __forceinline__ void cp4(uint32_t dst, const void* src) {
    asm volatile("cp.async.ca.shared.global [%0], [%1], 4;" :: "r"(dst), "l"(src));
}
__device__ __forceinline__ void cp_commit() { asm volatile("cp.async.commit_group;"); }
template <int N>
__device__ __forceinline__ void cp_wait() { asm volatile("cp.async.wait_group %0;" :: "n"(N)); }

// ---------------- single fused kernel: GEMM + per-mtile tree barrier + finish ----------------
__global__ void __launch_bounds__(256, 2)
fm_fused(const float* __restrict__ data,
         const float* __restrict__ embed,
         const float* __restrict__ bias,
         const float* __restrict__ gbias,
         float* __restrict__ out)
{
    extern __shared__ float sm[];
    float* As = sm;                       // [row][k] stride 132
    float* Bs = sm + 128 * A_STRIDE;      // [k][n]  stride 40

    const int t = threadIdx.x;
    const int w = t >> 5, lane = t & 31;
    const int g = lane >> 2, ctg = lane & 3;
    const int mtile = blockIdx.x & 7;
    const int ksplit = blockIdx.x >> 3;
    const int kbase = ksplit * K_PER_CTA;
    const float* arow0 = data + (size_t)(mtile * 128) * FF + kbase;

    const unsigned my_epoch = g_phase[mtile];   // snapshot BEFORE arriving

    // zero B pad columns (n=33..39); cp.async never writes them
    for (int i = t; i < K_PER_CTA * 7; i += 256) {
        const int k = i / 7, n = 33 + (i - k * 7);
        Bs[k * B_STRIDE + n] = 0.f;
    }

    // issue ALL loads up front, one commit group per 32-k chunk
    #pragma unroll
    for (int c = 0; c < NCHUNK; c++) {
        #pragma unroll
        for (int i = 0; i < 4; i++) {
            const int idx = t + i * 256;
            const int row = idx >> 3, kq = (idx & 7) << 2;
            cp16(smem_u32(&As[row * A_STRIDE + c * KC + kq]),
                 arow0 + (size_t)row * FF + c * KC + kq);
        }
        const int k = t >> 3, q4 = (t & 7) << 2;
        cp16(smem_u32(&Bs[(c * KC + k) * B_STRIDE + q4]),
             embed + (size_t)(kbase + c * KC + k) * DD + q4);
        if (t < KC)
            cp4(smem_u32(&Bs[(c * KC + t) * B_STRIDE + 32]), bias + kbase + c * KC + t);
        cp_commit();
    }

    float acc[NT][4];
    #pragma unroll
    for (int nt = 0; nt < NT; nt++)
        #pragma unroll
        for (int j = 0; j < 4; j++) acc[nt][j] = 0.f;

    const float* Aw = &As[(w * 16) * A_STRIDE];

    #pragma unroll
    for (int ch = 0; ch < NCHUNK; ch++) {
        if (ch == 0)      cp_wait<3>();
        else if (ch == 1) cp_wait<2>();
        else if (ch == 2) cp_wait<1>();
        else              cp_wait<0>();
        __syncthreads();

        #pragma unroll
        for (int ks = 0; ks < 4; ks++) {
            const int k0 = ch * KC + ks * 8;
            const uint32_t a0 = __float_as_uint(Aw[g * A_STRIDE + k0 + ctg]);
            const uint32_t a1 = __float_as_uint(Aw[(g + 8) * A_STRIDE + k0 + ctg]);
            const uint32_t a2 = __float_as_uint(Aw[g * A_STRIDE + k0 + ctg + 4]);
            const uint32_t a3 = __float_as_uint(Aw[(g + 8) * A_STRIDE + k0 + ctg + 4]);
            #pragma unroll
            for (int nt = 0; nt < NT; nt++) {
                const uint32_t b0 = __float_as_uint(Bs[(k0 + ctg) * B_STRIDE + nt * 8 + g]);
                const uint32_t b1 = __float_as_uint(Bs[(k0 + ctg + 4) * B_STRIDE + nt * 8 + g]);
                asm volatile(
                    "mma.sync.aligned.m16n8k8.row.col.f32.tf32.tf32.f32 "
                    "{%0,%1,%2,%3}, {%4,%5,%6,%7}, {%8,%9}, {%0,%1,%2,%3};"
                    : "+f"(acc[nt][0]), "+f"(acc[nt][1]), "+f"(acc[nt][2]), "+f"(acc[nt][3])
                    : "r"(a0), "r"(a1), "r"(a2), "r"(a3), "r"(b0), "r"(b1));
            }
        }
    }

    // epilogue: plain stores into this ksplit's private slab (n<=32 kept)
    float* pbase = g_part + (size_t)ksplit * BB * NBP;
    const int mbase = mtile * 128 + w * 16;
    #pragma unroll
    for (int nt = 0; nt < NT; nt++) {
        #pragma unroll
        for (int j = 0; j < 4; j++) {
            const int n = nt * 8 + 2 * ctg + (j & 1);
            const int m = mbase + g + ((j >> 1) << 3);
            if (n <= DD)
                pbase[(size_t)m * NBP + n] = acc[nt][j];
        }
    }

    // ---- per-mtile two-level tree barrier: 32 arrivals = 4 groups x 8 ----
    __threadfence();
    __syncthreads();
    if (t == 0) {
        const int grp = mtile * 4 + (ksplit >> 3);
        if (atomicAdd(&g_c1[grp], 1u) == 7u) {
            if (atomicAdd(&g_c2[mtile], 1u) == 3u) {
                g_c2[mtile] = 0u;
                #pragma unroll
                for (int i = 0; i < 4; i++) g_c1[mtile * 4 + i] = 0u;
                __threadfence();
                atomicAdd((unsigned*)&g_phase[mtile], 1u);   // release this mtile
            }
        }
        while (g_phase[mtile] == my_epoch) {}
    }
    __syncthreads();
    __threadfence();

    // ---- finish: warps 0-3 each own one row inside this mtile ----
    if (w < 4) {
        const int row = mtile * 128 + ksplit * 4 + w;
        float s = 0.f;
        #pragma unroll
        for (int k = 0; k < KSPLITS; k++)
            s += g_part[((size_t)k * BB + row) * NBP + lane];

        const float b = g_part[((size_t)lane * BB + row) * NBP + 32];  // lane = ksplit

        float v = s * s + b;
        #pragma unroll
        for (int o = 16; o; o >>= 1)
            v += __shfl_xor_sync(0xffffffffu, v, o);

        if (lane == 0)
            out[row] = 1.0f / (1.0f + __expf(-(gbias[0] + v)));
    }
}

extern "C" void kernel_launch(void* const* d_in, const int* in_sizes, int n_in,
                              void* d_out, int out_size)
{
    const float* data  = (const float*)d_in[0];
    const float* embed = (const float*)d_in[1];
    const float* bias  = (const float*)d_in[2];
    const float* gb    = (const float*)d_in[3];
    float* out = (float*)d_out;

    const int smem_bytes = SMEM_FLOATS * (int)sizeof(float);
    cudaFuncSetAttribute(fm_fused, cudaFuncAttributeMaxDynamicSharedMemorySize, smem_bytes);

    fm_fused<<<NCTAS, 256, smem_bytes>>>(data, embed, bias, gb, out);
}

// round 15
// speedup vs baseline: 1.3434x; 1.1830x over previous
#include <cuda_runtime.h>
#include <cstdint>
#include <cstddef>

#define BB 1024
#define FF 4096
#define DD 32
#define NT 4             // n-tiles of 8: n 0-31 embed (bias via FFMA on A-frags)
#define MTILES 8
#define KSPLITS 32
#define K_PER_CTA 128
#define KC 32
#define NCHUNK 4
#define A_STRIDE 132     // conflict-free, 16B aligned
#define B_STRIDE 40      // cols 0-31 embed, col 32 bias
#define NBP 36           // partials row stride (0-31 s, 32 bias)
#define SMEM_FLOATS (128 * A_STRIDE + K_PER_CTA * B_STRIDE)   // 86 KB

// non-atomic split-K partials: [ksplit][row][n]
__device__ float g_part[(size_t)KSPLITS * BB * NBP];

__device__ __forceinline__ uint32_t smem_u32(const void* p) {
    uint32_t a;
    asm("{ .reg .u64 t; cvta.to.shared.u64 t, %1; cvt.u32.u64 %0, t; }" : "=r"(a) : "l"(p));
    return a;
}
__device__ __forceinline__ void cp16(uint32_t dst, const void* src) {
    asm volatile("cp.async.cg.shared.global [%0], [%1], 16;" :: "r"(dst), "l"(src));
}
__device__ __forceinline__ void cp4(uint32_t dst, const void* src) {
    asm volatile("cp.async.ca.shared.global [%0], [%1], 4;" :: "r"(dst), "l"(src));
}
__device__ __forceinline__ void cp_commit() { asm volatile("cp.async.commit_group;"); }
template <int N>
__device__ __forceinline__ void cp_wait() { asm volatile("cp.async.wait_group %0;" :: "n"(N)); }

// ---------------- GEMM: tf32 mma.sync (R7 config), NT=4, PDL trigger ----------------
__global__ void __launch_bounds__(256, 2)
fm_gemm(const float* __restrict__ data,
        const float* __restrict__ embed,
        const float* __restrict__ bias)
{
    extern __shared__ float sm[];
    float* As = sm;                       // [row][k] stride 132
    float* Bs = sm + 128 * A_STRIDE;      // [k][n]  stride 40

    const int t = threadIdx.x;
    const int w = t >> 5, lane = t & 31;
    const int g = lane >> 2, ctg = lane & 3;
    const int mtile = blockIdx.x & 7;
    const int ksplit = blockIdx.x >> 3;
    const int kbase = ksplit * K_PER_CTA;
    const float* arow0 = data + (size_t)(mtile * 128) * FF + kbase;

    // issue ALL loads up front, one commit group per 32-k chunk
    #pragma unroll
    for (int c = 0; c < NCHUNK; c++) {
        #pragma unroll
        for (int i = 0; i < 4; i++) {
            const int idx = t + i * 256;
            const int row = idx >> 3, kq = (idx & 7) << 2;
            cp16(smem_u32(&As[row * A_STRIDE + c * KC + kq]),
                 arow0 + (size_t)row * FF + c * KC + kq);
        }
        const int k = t >> 3, q4 = (t & 7) << 2;
        cp16(smem_u32(&Bs[(c * KC + k) * B_STRIDE + q4]),
             embed + (size_t)(kbase + c * KC + k) * DD + q4);
        if (t < KC)
            cp4(smem_u32(&Bs[(c * KC + t) * B_STRIDE + 32]), bias + kbase + c * KC + t);
        cp_commit();
    }

    float acc[NT][4];
    #pragma unroll
    for (int nt = 0; nt < NT; nt++)
        #pragma unroll
        for (int j = 0; j < 4; j++) acc[nt][j] = 0.f;
    float bacc0 = 0.f, bacc1 = 0.f;

    const float* Aw = &As[(w * 16) * A_STRIDE];

    #pragma unroll
    for (int ch = 0; ch < NCHUNK; ch++) {
        if (ch == 0)      cp_wait<3>();
        else if (ch == 1) cp_wait<2>();
        else if (ch == 2) cp_wait<1>();
        else              cp_wait<0>();
        __syncthreads();

        #pragma unroll
        for (int ks = 0; ks < 4; ks++) {
            const int k0 = ch * KC + ks * 8;
            const uint32_t a0 = __float_as_uint(Aw[g * A_STRIDE + k0 + ctg]);
            const uint32_t a1 = __float_as_uint(Aw[(g + 8) * A_STRIDE + k0 + ctg]);
            const uint32_t a2 = __float_as_uint(Aw[g * A_STRIDE + k0 + ctg + 4]);
            const uint32_t a3 = __float_as_uint(Aw[(g + 8) * A_STRIDE + k0 + ctg + 4]);

            // bias column via scalar FFMA (verified mapping: a0/a2 -> row g, a1/a3 -> row g+8)
            const float bk  = Bs[(k0 + ctg) * B_STRIDE + 32];
            const float bk4 = Bs[(k0 + ctg + 4) * B_STRIDE + 32];
            bacc0 = fmaf(__uint_as_float(a0), bk,  bacc0);
            bacc0 = fmaf(__uint_as_float(a2), bk4, bacc0);
            bacc1 = fmaf(__uint_as_float(a1), bk,  bacc1);
            bacc1 = fmaf(__uint_as_float(a3), bk4, bacc1);

            #pragma unroll
            for (int nt = 0; nt < NT; nt++) {
                const uint32_t b0 = __float_as_uint(Bs[(k0 + ctg) * B_STRIDE + nt * 8 + g]);
                const uint32_t b1 = __float_as_uint(Bs[(k0 + ctg + 4) * B_STRIDE + nt * 8 + g]);
                asm volatile(
                    "mma.sync.aligned.m16n8k8.row.col.f32.tf32.tf32.f32 "
                    "{%0,%1,%2,%3}, {%4,%5,%6,%7}, {%8,%9}, {%0,%1,%2,%3};"
                    : "+f"(acc[nt][0]), "+f"(acc[nt][1]), "+f"(acc[nt][2]), "+f"(acc[nt][3])
                    : "r"(a0), "r"(a1), "r"(a2), "r"(a3), "r"(b0), "r"(b1));
            }
        }
    }

    // epilogue: plain stores into this ksplit's private slab
    float* pbase = g_part + (size_t)ksplit * BB * NBP;
    const int mbase = mtile * 128 + w * 16;
    #pragma unroll
    for (int nt = 0; nt < NT; nt++) {
        #pragma unroll
        for (int j = 0; j < 4; j++) {
            const int n = nt * 8 + 2 * ctg + (j & 1);
            const int m = mbase + g + ((j >> 1) << 3);
            pbase[(size_t)m * NBP + n] = acc[nt][j];
        }
    }
    // bias partials: quad-reduce, ctg==0 lanes store
    bacc0 += __shfl_xor_sync(0xffffffffu, bacc0, 1);
    bacc0 += __shfl_xor_sync(0xffffffffu, bacc0, 2);
    bacc1 += __shfl_xor_sync(0xffffffffu, bacc1, 1);
    bacc1 += __shfl_xor_sync(0xffffffffu, bacc1, 2);
    if (ctg == 0) {
        pbase[(size_t)(mbase + g) * NBP + 32]     = bacc0;
        pbase[(size_t)(mbase + g + 8) * NBP + 32] = bacc1;
    }

    // PDL: allow the dependent finisher grid to begin launching
    asm volatile("griddepcontrol.launch_dependents;");
}

// ---------------- finisher: PDL wait, reduce 32 ksplits, sigmoid ----------------
__global__ void __launch_bounds__(256)
fm_finish(const float* __restrict__ gbias, float* __restrict__ out)
{
    asm volatile("griddepcontrol.wait;" ::: "memory");

    const int w = threadIdx.x >> 5, lane = threadIdx.x & 31;
    const int row = blockIdx.x * 8 + w;

    float s = 0.f;
    #pragma unroll
    for (int k = 0; k < KSPLITS; k++)
        s += g_part[((size_t)k * BB + row) * NBP + lane];

    const float b = g_part[((size_t)lane * BB + row) * NBP + 32];  // lane = ksplit

    float t = s * s + b;
    #pragma unroll
    for (int o = 16; o; o >>= 1)
        t += __shfl_xor_sync(0xffffffffu, t, o);

    if (lane == 0)
        out[row] = 1.0f / (1.0f + __expf(-(gbias[0] + t)));
}

extern "C" void kernel_launch(void* const* d_in, const int* in_sizes, int n_in,
                              void* d_out, int out_size)
{
    const float* data  = (const float*)d_in[0];
    const float* embed = (const float*)d_in[1];
    const float* bias  = (const float*)d_in[2];
    const float* gb    = (const float*)d_in[3];
    float* out = (float*)d_out;

    const int smem_bytes = SMEM_FLOATS * (int)sizeof(float);
    cudaFuncSetAttribute(fm_gemm, cudaFuncAttributeMaxDynamicSharedMemorySize, smem_bytes);

    fm_gemm<<<MTILES * KSPLITS, 256, smem_bytes>>>(data, embed, bias);

    // dependent launch: overlap finisher launch latency with gemm tail
    cudaLaunchConfig_t cfg = {};
    cfg.gridDim = dim3(BB / 8);
    cfg.blockDim = dim3(256);
    cfg.dynamicSmemBytes = 0;
    cfg.stream = 0;
    cudaLaunchAttribute attr[1];
    attr[0].id = cudaLaunchAttributeProgrammaticStreamSerialization;
    attr[0].val.programmaticStreamSerializationAllowed = 1;
    cfg.attrs = attr;
    cfg.numAttrs = 1;
    cudaLaunchKernelEx(&cfg, fm_finish, gb, out);
}